// round 10
// baseline (speedup 1.0000x reference)
#include <cuda_runtime.h>
#include <cuda_fp16.h>
#include <cstdint>
#include <math.h>

// Problem constants (FP_Layer: B=8, N=8192, M=2048, C1=128, C2=256, H=256)
#define BB    8
#define NPTS  8192
#define MPTS  2048
#define C1    128
#define C2    256
#define HDIM  256
#define CIN   384
#define ROWS  (BB * NPTS)      // 65536
#define NPART 2048             // 512 CTAs * 4 row-quarters
#define KC    64               // K-chunk per stage

// ---------------- scratch (device globals; no allocation allowed) ----------
__device__ float g_y1[(size_t)ROWS * HDIM];                 // 64 MB fp32
__device__ __align__(16) __half g_x1[(size_t)ROWS * CIN];   // 48 MB fp16
__device__ __align__(16) __half g_x2[(size_t)ROWS * HDIM];  // 32 MB fp16
__device__ int   g_idx[ROWS * 3];
__device__ float g_w[ROWS * 3];
__device__ float g_psum[HDIM * NPART];          // [col][part] transposed
__device__ float g_psq[HDIM * NPART];
__device__ float g_a[HDIM];
__device__ float g_c[HDIM];
__device__ __align__(16) __half g_w1h[256 * 384];
__device__ __align__(16) __half g_w2h[256 * 256];

// ================= PTX helpers (baseline ISA, OK on compute_103) ============
__device__ __forceinline__ uint32_t smem_u32(const void* p) {
    uint32_t a;
    asm("{ .reg .u64 t; cvta.to.shared.u64 t, %1; cvt.u32.u64 %0, t; }" : "=r"(a) : "l"(p));
    return a;
}
__device__ __forceinline__ void cpa16(uint32_t s, const void* g) {
    asm volatile("cp.async.cg.shared.global [%0], [%1], 16;" :: "r"(s), "l"(g));
}
#define CP_COMMIT() asm volatile("cp.async.commit_group;" ::: "memory")
#define CP_WAIT2()  asm volatile("cp.async.wait_group 2;" ::: "memory")
#define CP_WAIT1()  asm volatile("cp.async.wait_group 1;" ::: "memory")
#define CP_WAIT0()  asm volatile("cp.async.wait_group 0;" ::: "memory")

__device__ __forceinline__ void ldsm4(uint32_t* r, uint32_t addr) {
    asm volatile("ldmatrix.sync.aligned.m8n8.x4.shared.b16 {%0,%1,%2,%3}, [%4];"
                 : "=r"(r[0]), "=r"(r[1]), "=r"(r[2]), "=r"(r[3]) : "r"(addr));
}
__device__ __forceinline__ void mma_f16(float* c, const uint32_t* a, const uint32_t* b) {
    asm volatile(
        "mma.sync.aligned.m16n8k16.row.col.f32.f16.f16.f32 "
        "{%0,%1,%2,%3}, {%4,%5,%6,%7}, {%8,%9}, {%0,%1,%2,%3};"
        : "+f"(c[0]), "+f"(c[1]), "+f"(c[2]), "+f"(c[3])
        : "r"(a[0]), "r"(a[1]), "r"(a[2]), "r"(a[3]), "r"(b[0]), "r"(b[1]));
}

// ---------------- 0) convert W to fp16 --------------------------------------
__global__ void __launch_bounds__(256) prep_w_kernel(const float* __restrict__ W1,
                                                     const float* __restrict__ W2) {
    int i = blockIdx.x * 256 + threadIdx.x;   // grid covers 256*384
    g_w1h[i] = __float2half_rn(W1[i]);
    if (i < 256 * 256) g_w2h[i] = __float2half_rn(W2[i]);
}

// ---------------- 1) 3-NN over xyz2 (4 independent compare chains) ---------
__global__ void __launch_bounds__(256) knn_kernel(const float* __restrict__ xyz1,
                                                  const float* __restrict__ xyz2) {
    __shared__ float4 s2[MPTS];               // x,y,z,|.|^2  (32KB)
    int b    = blockIdx.x >> 5;
    int tile = blockIdx.x & 31;
    const float* x2 = xyz2 + (size_t)b * MPTS * 3;
    for (int i = threadIdx.x; i < MPTS; i += 256) {
        float x = x2[i * 3 + 0], y = x2[i * 3 + 1], z = x2[i * 3 + 2];
        s2[i] = make_float4(x, y, z, x * x + y * y + z * z);
    }
    __syncthreads();

    int n = tile * 256 + threadIdx.x;
    int r = b * NPTS + n;
    float px = xyz1[(size_t)r * 3 + 0];
    float py = xyz1[(size_t)r * 3 + 1];
    float pz = xyz1[(size_t)r * 3 + 2];
    float pn = px * px + py * py + pz * pz;

    float cd[4][3];
    int   ci[4][3];
    #pragma unroll
    for (int j = 0; j < 4; j++) {
        cd[j][0] = cd[j][1] = cd[j][2] = 3.4e38f;
        ci[j][0] = ci[j][1] = ci[j][2] = 0;
    }
    for (int m = 0; m < MPTS; m += 4) {
        #pragma unroll
        for (int j = 0; j < 4; j++) {
            float4 t = s2[m + j];
            // identical formula to reference: |a|^2 + |b|^2 - 2 a.b
            float d = (pn + t.w) - 2.f * (px * t.x + py * t.y + pz * t.z);
            if (d < cd[j][2]) {
                if (d < cd[j][1]) {
                    cd[j][2] = cd[j][1]; ci[j][2] = ci[j][1];
                    if (d < cd[j][0]) {
                        cd[j][1] = cd[j][0]; ci[j][1] = ci[j][0];
                        cd[j][0] = d; ci[j][0] = m + j;
                    } else { cd[j][1] = d; ci[j][1] = m + j; }
                } else { cd[j][2] = d; ci[j][2] = m + j; }
            }
        }
    }
    // exact lexicographic (d, idx) merge of 12 candidates -> 3 smallest
    float md[12]; int mi[12];
    #pragma unroll
    for (int j = 0; j < 4; j++)
        #pragma unroll
        for (int k = 0; k < 3; k++) { md[j * 3 + k] = cd[j][k]; mi[j * 3 + k] = ci[j][k]; }
    float outd[3]; int outi[3];
    #pragma unroll
    for (int s = 0; s < 3; s++) {
        float bd = 3.5e38f; int bi = 0x7fffffff; int bk = 0;
        #pragma unroll
        for (int k = 0; k < 12; k++) {
            bool take = (md[k] < bd) || (md[k] == bd && mi[k] < bi);
            if (take) { bd = md[k]; bi = mi[k]; bk = k; }
        }
        outd[s] = bd; outi[s] = bi;
        md[bk] = 3.5e38f; mi[bk] = 0x7fffffff;
    }
    float r0 = 1.f / (outd[0] + 1e-8f);
    float r1 = 1.f / (outd[1] + 1e-8f);
    float r2 = 1.f / (outd[2] + 1e-8f);
    float s  = (r0 + r1) + r2;
    g_idx[r * 3 + 0] = outi[0]; g_idx[r * 3 + 1] = outi[1]; g_idx[r * 3 + 2] = outi[2];
    g_w[r * 3 + 0] = r0 / s; g_w[r * 3 + 1] = r1 / s; g_w[r * 3 + 2] = r2 / s;
}

// ---------------- 2) build x1 = fp16([points1 | interp(points2)]) -----------
__global__ void __launch_bounds__(256) prep_x1_kernel(const float* __restrict__ points1,
                                                      const float* __restrict__ P2) {
    const int idx = blockIdx.x * 256 + threadIdx.x;
    const int row = idx / 48;
    const int g8  = (idx % 48) * 8;
    __half2 out[4];
    if (g8 < C1) {
        const float* src = points1 + (size_t)row * C1 + g8;
        float4 f0 = *(const float4*)(src);
        float4 f1 = *(const float4*)(src + 4);
        out[0] = __floats2half2_rn(f0.x, f0.y);
        out[1] = __floats2half2_rn(f0.z, f0.w);
        out[2] = __floats2half2_rn(f1.x, f1.y);
        out[3] = __floats2half2_rn(f1.z, f1.w);
    } else {
        const int cc = g8 - C1;
        const float* p2b = P2 + (size_t)(row >> 13) * MPTS * C2;   // row / NPTS
        const float w0 = g_w[row * 3 + 0], w1 = g_w[row * 3 + 1], w2 = g_w[row * 3 + 2];
        const float* q0 = p2b + (size_t)g_idx[row * 3 + 0] * C2 + cc;
        const float* q1 = p2b + (size_t)g_idx[row * 3 + 1] * C2 + cc;
        const float* q2 = p2b + (size_t)g_idx[row * 3 + 2] * C2 + cc;
        #pragma unroll
        for (int h = 0; h < 2; h++) {
            float4 a = *(const float4*)(q0 + 4 * h);
            float4 b = *(const float4*)(q1 + 4 * h);
            float4 d = *(const float4*)(q2 + 4 * h);
            float v0 = a.x * w0 + b.x * w1 + d.x * w2;
            float v1 = a.y * w0 + b.y * w1 + d.y * w2;
            float v2 = a.z * w0 + b.z * w1 + d.z * w2;
            float v3 = a.w * w0 + b.w * w1 + d.w * w2;
            out[2 * h + 0] = __floats2half2_rn(v0, v1);
            out[2 * h + 1] = __floats2half2_rn(v2, v3);
        }
    }
    *(uint4*)(g_x1 + (size_t)row * CIN + g8) = *(uint4*)out;
}

// ---------------- 3) build x2 = fp16(relu(bn(y1))) --------------------------
__global__ void __launch_bounds__(256) prep_x2_kernel() {
    __shared__ float sA[HDIM], sC[HDIM];
    sA[threadIdx.x] = g_a[threadIdx.x];
    sC[threadIdx.x] = g_c[threadIdx.x];
    __syncthreads();
    const int idx = blockIdx.x * 256 + threadIdx.x;
    const int row = idx / 32;
    const int c8  = (idx % 32) * 8;
    const float* src = g_y1 + (size_t)row * HDIM + c8;
    float4 f0 = *(const float4*)(src);
    float4 f1 = *(const float4*)(src + 4);
    __half2 out[4];
    out[0] = __floats2half2_rn(fmaxf(f0.x * sA[c8+0] + sC[c8+0], 0.f),
                               fmaxf(f0.y * sA[c8+1] + sC[c8+1], 0.f));
    out[1] = __floats2half2_rn(fmaxf(f0.z * sA[c8+2] + sC[c8+2], 0.f),
                               fmaxf(f0.w * sA[c8+3] + sC[c8+3], 0.f));
    out[2] = __floats2half2_rn(fmaxf(f1.x * sA[c8+4] + sC[c8+4], 0.f),
                               fmaxf(f1.y * sA[c8+5] + sC[c8+5], 0.f));
    out[3] = __floats2half2_rn(fmaxf(f1.z * sA[c8+6] + sC[c8+6], 0.f),
                               fmaxf(f1.w * sA[c8+7] + sC[c8+7], 0.f));
    *(uint4*)(g_x2 + (size_t)row * HDIM + c8) = *(uint4*)out;
}

// ---------------- 4) streaming FP16 HMMA GEMM  C = A * W^T + bias -----------
// CTA 128(M) x 256(N), 512 threads / 16 warps, warp tile 32x64, KC=64,
// 3 cp.async stages. Halves W L2-traffic vs M=64 tiling.
#define PITCHB    144                      // bytes per row (72 halves)
#define OFF_BIAS  0
#define OFF_T     1024
#define A_SZ      (128 * PITCHB)           // 18432
#define B_SZ      (256 * PITCHB)           // 36864
#define STG_SZ    (A_SZ + B_SZ)            // 55296
#define OFF_A(s)  (OFF_T + (s) * STG_SZ)
#define OFF_B(s)  (OFF_A(s) + A_SZ)
#define SMEM_SZ   (OFF_T + 3 * STG_SZ)     // 166912

template <int K>
__global__ void __launch_bounds__(512, 1) gemm_f16(const __half* __restrict__ Ah,
                                                   const __half* __restrict__ WH,
                                                   const float* __restrict__ bias,
                                                   float* __restrict__ dst_) {
    constexpr int NC = K / KC;
    extern __shared__ char smem[];
    const uint32_t sb = smem_u32(smem);
    const int tid = threadIdx.x, wid = tid >> 5, lane = tid & 31;
    const int rowBase = blockIdx.x * 128;

    float* sBias = (float*)(smem + OFF_BIAS);
    if (tid < 256) sBias[tid] = bias[tid];
    __syncthreads();

    auto fillB = [&](int c, int s) {
        const int kt = c * KC;
        const uint32_t base = sb + OFF_B(s);
        #pragma unroll
        for (int it = 0; it < 4; it++) {
            const int idx = tid + 512 * it;       // 0..2047
            const int n = idx >> 3, j = idx & 7;  // W row, 16B chunk
            cpa16(base + (uint32_t)(n * PITCHB + j * 16),
                  WH + (size_t)n * K + kt + j * 8);
        }
    };
    auto fillA = [&](int c, int s) {
        const int kt = c * KC;
        const uint32_t base = sb + OFF_A(s);
        #pragma unroll
        for (int it = 0; it < 2; it++) {
            const int idx = tid + 512 * it;       // 0..1023
            const int n = idx >> 3, j = idx & 7;  // tile row, 16B chunk
            cpa16(base + (uint32_t)(n * PITCHB + j * 16),
                  Ah + (size_t)(rowBase + n) * K + kt + j * 8);
        }
    };

    // ---- warp tiling: 4 row-quarters (32 rows) x 4 col-groups (64 cols)
    const int rh = wid & 3;
    const int cg = wid >> 2;
    const int nb = cg * 64;

    // ---- accumulators init = bias (folded epilogue add)
    float acc[2][8][4];
    #pragma unroll
    for (int nt = 0; nt < 8; nt++) {
        const float b0 = sBias[nb + nt * 8 + 2 * (lane & 3)];
        const float b1 = sBias[nb + nt * 8 + 2 * (lane & 3) + 1];
        #pragma unroll
        for (int mt = 0; mt < 2; mt++) {
            acc[mt][nt][0] = b0; acc[mt][nt][1] = b1;
            acc[mt][nt][2] = b0; acc[mt][nt][3] = b1;
        }
    }

    // ldmatrix per-lane address parts
    const uint32_t aRow = (uint32_t)(((lane >> 3) & 1) * 8 + (lane & 7));
    const uint32_t aK   = (uint32_t)((lane >> 4) * 8);
    const uint32_t bRow = (uint32_t)((lane >> 4) * 8 + (lane & 7));
    const uint32_t bK   = (uint32_t)(((lane >> 3) & 1) * 8);

    // ---- prologue: stages 0,1 in flight
    fillA(0, 0); fillB(0, 0); CP_COMMIT();
    fillA(1, 1); fillB(1, 1); CP_COMMIT();

    #pragma unroll 1
    for (int c = 0; c < NC; c++) {
        const int s = c % 3;
        if (c > 0) __syncthreads();             // stage (c+2)%3 readers done
        if (c + 2 < NC) {
            const int s2 = (c + 2) % 3;
            fillA(c + 2, s2); fillB(c + 2, s2); CP_COMMIT();
            CP_WAIT2();
        } else if (c + 1 < NC) {
            CP_WAIT1();
        } else {
            CP_WAIT0();
        }
        __syncthreads();                        // stage c visible to all

        const uint32_t baseA = sb + OFF_A(0) + (uint32_t)s * STG_SZ;
        const uint32_t baseB = baseA + A_SZ;

        #pragma unroll
        for (int kk = 0; kk < 4; kk++) {
            uint32_t a[2][4], bh[16];
            #pragma unroll
            for (int mt = 0; mt < 2; mt++)
                ldsm4(a[mt], baseA + (rh * 32 + mt * 16 + aRow) * PITCHB + (kk * 16 + aK) * 2);
            #pragma unroll
            for (int p = 0; p < 4; p++)
                ldsm4(&bh[p * 4], baseB + (nb + p * 16 + bRow) * PITCHB + (kk * 16 + bK) * 2);
            #pragma unroll
            for (int mt = 0; mt < 2; mt++)
                #pragma unroll
                for (int nt = 0; nt < 8; nt++) {
                    // f16 B fragment = CONSECUTIVE regs within the 16-row group:
                    // nt even -> {r0,r1} (rows 0-8), nt odd -> {r2,r3} (rows 8-16)
                    mma_f16(acc[mt][nt], a[mt], &bh[(nt >> 1) * 4 + (nt & 1) * 2]);
                }
        }
    }

    // ---- epilogue 1: per-(CTA,row-quarter) BN partials (transposed)
    {
        const int part = blockIdx.x * 4 + rh;
        #pragma unroll
        for (int nt = 0; nt < 8; nt++) {
            float s0 = 0.f, s1 = 0.f, q0 = 0.f, q1 = 0.f;
            #pragma unroll
            for (int mt = 0; mt < 2; mt++) {
                float v0 = acc[mt][nt][0], v1 = acc[mt][nt][1];
                float v2 = acc[mt][nt][2], v3 = acc[mt][nt][3];
                s0 += v0 + v2;  s1 += v1 + v3;
                q0 += v0 * v0 + v2 * v2;  q1 += v1 * v1 + v3 * v3;
            }
            #pragma unroll
            for (int o = 4; o < 32; o <<= 1) {
                s0 += __shfl_xor_sync(0xffffffffu, s0, o);
                s1 += __shfl_xor_sync(0xffffffffu, s1, o);
                q0 += __shfl_xor_sync(0xffffffffu, q0, o);
                q1 += __shfl_xor_sync(0xffffffffu, q1, o);
            }
            if (lane < 4) {
                const int col = nb + nt * 8 + 2 * lane;
                g_psum[(size_t)col * NPART + part]       = s0;
                g_psum[(size_t)(col + 1) * NPART + part] = s1;
                g_psq[(size_t)col * NPART + part]        = q0;
                g_psq[(size_t)(col + 1) * NPART + part]  = q1;
            }
        }
    }

    // ---- epilogue 2: store fp32 y
    #pragma unroll
    for (int mt = 0; mt < 2; mt++) {
        const int row = rowBase + rh * 32 + mt * 16 + (lane >> 2);
        #pragma unroll
        for (int nt = 0; nt < 8; nt++) {
            const int col = nb + nt * 8 + 2 * (lane & 3);
            float2 v0 = {acc[mt][nt][0], acc[mt][nt][1]};
            float2 v1 = {acc[mt][nt][2], acc[mt][nt][3]};
            *(float2*)(dst_ + (size_t)row * HDIM + col)       = v0;
            *(float2*)(dst_ + (size_t)(row + 8) * HDIM + col) = v1;
        }
    }
}

// ---------------- 5) BN stats final reduce (one block per channel) ----------
__global__ void __launch_bounds__(256) stats_final_kernel(const float* __restrict__ gamma,
                                                          const float* __restrict__ beta) {
    const int ch = blockIdx.x;
    const int t  = threadIdx.x;
    const float* ps = g_psum + (size_t)ch * NPART;
    const float* pq = g_psq + (size_t)ch * NPART;
    float s = 0.f, q = 0.f;
    #pragma unroll
    for (int k = 0; k < NPART / 256; k++) {
        s += ps[t + 256 * k];
        q += pq[t + 256 * k];
    }
    __shared__ float ss[256], sq[256];
    ss[t] = s; sq[t] = q;
    __syncthreads();
    #pragma unroll
    for (int o = 128; o >= 32; o >>= 1) {
        if (t < o) { ss[t] += ss[t + o]; sq[t] += sq[t + o]; }
        __syncthreads();
    }
    if (t < 32) {
        s = ss[t]; q = sq[t];
        #pragma unroll
        for (int o = 16; o > 0; o >>= 1) {
            s += __shfl_xor_sync(0xffffffffu, s, o);
            q += __shfl_xor_sync(0xffffffffu, q, o);
        }
        if (t == 0) {
            const float mean = s * (1.f / (float)ROWS);
            const float var  = q * (1.f / (float)ROWS) - mean * mean;
            const float a    = gamma[ch] * rsqrtf(var + 1e-5f);
            g_a[ch] = a;
            g_c[ch] = beta[ch] - mean * a;
        }
    }
}

// ---------------- 6) in-place bn+relu on d_out ------------------------------
__global__ void __launch_bounds__(256) bnrelu_kernel(float* __restrict__ out) {
    size_t i = (size_t)blockIdx.x * 256 + threadIdx.x;   // float4 index
    float4* o4 = (float4*)out;
    float4 v = o4[i];
    int c = (int)((i << 2) & (HDIM - 1));
    v.x = fmaxf(v.x * g_a[c + 0] + g_c[c + 0], 0.f);
    v.y = fmaxf(v.y * g_a[c + 1] + g_c[c + 1], 0.f);
    v.z = fmaxf(v.z * g_a[c + 2] + g_c[c + 2], 0.f);
    v.w = fmaxf(v.w * g_a[c + 3] + g_c[c + 3], 0.f);
    o4[i] = v;
}

// ---------------- host ------------------------------------------------------
extern "C" void kernel_launch(void* const* d_in, const int* in_sizes, int n_in,
                              void* d_out, int out_size) {
    const float* xyz1    = (const float*)d_in[0];
    const float* xyz2    = (const float*)d_in[1];
    const float* points1 = (const float*)d_in[2];
    const float* points2 = (const float*)d_in[3];
    const float* W1      = (const float*)d_in[4];
    const float* b1      = (const float*)d_in[5];
    const float* gamma1  = (const float*)d_in[6];
    const float* beta1   = (const float*)d_in[7];
    const float* W2      = (const float*)d_in[8];
    const float* b2      = (const float*)d_in[9];
    const float* gamma2  = (const float*)d_in[10];
    const float* beta2   = (const float*)d_in[11];
    float* out = (float*)d_out;

    cudaFuncSetAttribute(gemm_f16<CIN>,  cudaFuncAttributeMaxDynamicSharedMemorySize, SMEM_SZ);
    cudaFuncSetAttribute(gemm_f16<HDIM>, cudaFuncAttributeMaxDynamicSharedMemorySize, SMEM_SZ);

    __half *x1p = nullptr, *x2p = nullptr, *w1p = nullptr, *w2p = nullptr;
    float *y1p = nullptr;
    cudaGetSymbolAddress((void**)&x1p, g_x1);
    cudaGetSymbolAddress((void**)&x2p, g_x2);
    cudaGetSymbolAddress((void**)&w1p, g_w1h);
    cudaGetSymbolAddress((void**)&w2p, g_w2h);
    cudaGetSymbolAddress((void**)&y1p, g_y1);

    prep_w_kernel<<<(256 * 384) / 256, 256>>>(W1, W2);
    knn_kernel<<<BB * (NPTS / 256), 256>>>(xyz1, xyz2);
    prep_x1_kernel<<<(ROWS * 48) / 256, 256>>>(points1, points2);

    gemm_f16<CIN><<<ROWS / 128, 512, SMEM_SZ>>>(x1p, w1p, b1, y1p);
    stats_final_kernel<<<HDIM, 256>>>(gamma1, beta1);
    prep_x2_kernel<<<(ROWS * 32) / 256, 256>>>();

    gemm_f16<HDIM><<<ROWS / 128, 512, SMEM_SZ>>>(x2p, w2p, b2, out);
    stats_final_kernel<<<HDIM, 256>>>(gamma2, beta2);

    bnrelu_kernel<<<(ROWS * HDIM / 4) / 256, 256>>>(out);
}

// round 11
// speedup vs baseline: 1.0814x; 1.0814x over previous
#include <cuda_runtime.h>
#include <cuda_fp16.h>
#include <cstdint>
#include <math.h>

// Problem constants (FP_Layer: B=8, N=8192, M=2048, C1=128, C2=256, H=256)
#define BB    8
#define NPTS  8192
#define MPTS  2048
#define C1    128
#define C2    256
#define HDIM  256
#define CIN   384
#define ROWS  (BB * NPTS)      // 65536
#define NPART 1024             // 512 m-tiles * 2 row-groups
#define KC    64               // K-chunk per stage

// ---------------- scratch (device globals; no allocation allowed) ----------
__device__ float g_y1[(size_t)ROWS * HDIM];                 // 64 MB fp32
__device__ __align__(16) __half g_x1[(size_t)ROWS * CIN];   // 48 MB fp16
__device__ __align__(16) __half g_x2[(size_t)ROWS * HDIM];  // 32 MB fp16
__device__ int   g_idx[ROWS * 3];
__device__ float g_w[ROWS * 3];
__device__ float g_psum[HDIM * NPART];          // [col][part] transposed
__device__ float g_psq[HDIM * NPART];
__device__ float g_a[HDIM];
__device__ float g_c[HDIM];
__device__ __align__(16) __half g_w1h[256 * 384];
__device__ __align__(16) __half g_w2h[256 * 256];

// ================= PTX helpers (baseline ISA, OK on compute_103) ============
__device__ __forceinline__ uint32_t smem_u32(const void* p) {
    uint32_t a;
    asm("{ .reg .u64 t; cvta.to.shared.u64 t, %1; cvt.u32.u64 %0, t; }" : "=r"(a) : "l"(p));
    return a;
}
__device__ __forceinline__ void cpa16(uint32_t s, const void* g) {
    asm volatile("cp.async.cg.shared.global [%0], [%1], 16;" :: "r"(s), "l"(g));
}
#define CP_COMMIT() asm volatile("cp.async.commit_group;" ::: "memory")
#define CP_WAIT1()  asm volatile("cp.async.wait_group 1;" ::: "memory")
#define CP_WAIT0()  asm volatile("cp.async.wait_group 0;" ::: "memory")

__device__ __forceinline__ void ldsm4(uint32_t* r, uint32_t addr) {
    asm volatile("ldmatrix.sync.aligned.m8n8.x4.shared.b16 {%0,%1,%2,%3}, [%4];"
                 : "=r"(r[0]), "=r"(r[1]), "=r"(r[2]), "=r"(r[3]) : "r"(addr));
}
__device__ __forceinline__ void mma_f16(float* c, const uint32_t* a, const uint32_t* b) {
    asm volatile(
        "mma.sync.aligned.m16n8k16.row.col.f32.f16.f16.f32 "
        "{%0,%1,%2,%3}, {%4,%5,%6,%7}, {%8,%9}, {%0,%1,%2,%3};"
        : "+f"(c[0]), "+f"(c[1]), "+f"(c[2]), "+f"(c[3])
        : "r"(a[0]), "r"(a[1]), "r"(a[2]), "r"(a[3]), "r"(b[0]), "r"(b[1]));
}

// ---------------- 0) convert W to fp16 --------------------------------------
__global__ void __launch_bounds__(256) prep_w_kernel(const float* __restrict__ W1,
                                                     const float* __restrict__ W2) {
    int i = blockIdx.x * 256 + threadIdx.x;   // grid covers 256*384
    g_w1h[i] = __float2half_rn(W1[i]);
    if (i < 256 * 256) g_w2h[i] = __float2half_rn(W2[i]);
}

// ---------------- 1) 3-NN over xyz2 (4 independent compare chains) ---------
__global__ void __launch_bounds__(256) knn_kernel(const float* __restrict__ xyz1,
                                                  const float* __restrict__ xyz2) {
    __shared__ float4 s2[MPTS];               // x,y,z,|.|^2  (32KB)
    int b    = blockIdx.x >> 5;
    int tile = blockIdx.x & 31;
    const float* x2 = xyz2 + (size_t)b * MPTS * 3;
    for (int i = threadIdx.x; i < MPTS; i += 256) {
        float x = x2[i * 3 + 0], y = x2[i * 3 + 1], z = x2[i * 3 + 2];
        s2[i] = make_float4(x, y, z, x * x + y * y + z * z);
    }
    __syncthreads();

    int n = tile * 256 + threadIdx.x;
    int r = b * NPTS + n;
    float px = xyz1[(size_t)r * 3 + 0];
    float py = xyz1[(size_t)r * 3 + 1];
    float pz = xyz1[(size_t)r * 3 + 2];
    float pn = px * px + py * py + pz * pz;

    float cd[4][3];
    int   ci[4][3];
    #pragma unroll
    for (int j = 0; j < 4; j++) {
        cd[j][0] = cd[j][1] = cd[j][2] = 3.4e38f;
        ci[j][0] = ci[j][1] = ci[j][2] = 0;
    }
    for (int m = 0; m < MPTS; m += 4) {
        #pragma unroll
        for (int j = 0; j < 4; j++) {
            float4 t = s2[m + j];
            // identical formula to reference: |a|^2 + |b|^2 - 2 a.b
            float d = (pn + t.w) - 2.f * (px * t.x + py * t.y + pz * t.z);
            if (d < cd[j][2]) {
                if (d < cd[j][1]) {
                    cd[j][2] = cd[j][1]; ci[j][2] = ci[j][1];
                    if (d < cd[j][0]) {
                        cd[j][1] = cd[j][0]; ci[j][1] = ci[j][0];
                        cd[j][0] = d; ci[j][0] = m + j;
                    } else { cd[j][1] = d; ci[j][1] = m + j; }
                } else { cd[j][2] = d; ci[j][2] = m + j; }
            }
        }
    }
    // exact lexicographic (d, idx) merge of 12 candidates -> 3 smallest
    float md[12]; int mi[12];
    #pragma unroll
    for (int j = 0; j < 4; j++)
        #pragma unroll
        for (int k = 0; k < 3; k++) { md[j * 3 + k] = cd[j][k]; mi[j * 3 + k] = ci[j][k]; }
    float outd[3]; int outi[3];
    #pragma unroll
    for (int s = 0; s < 3; s++) {
        float bd = 3.5e38f; int bi = 0x7fffffff; int bk = 0;
        #pragma unroll
        for (int k = 0; k < 12; k++) {
            bool take = (md[k] < bd) || (md[k] == bd && mi[k] < bi);
            if (take) { bd = md[k]; bi = mi[k]; bk = k; }
        }
        outd[s] = bd; outi[s] = bi;
        md[bk] = 3.5e38f; mi[bk] = 0x7fffffff;
    }
    float r0 = 1.f / (outd[0] + 1e-8f);
    float r1 = 1.f / (outd[1] + 1e-8f);
    float r2 = 1.f / (outd[2] + 1e-8f);
    float s  = (r0 + r1) + r2;
    g_idx[r * 3 + 0] = outi[0]; g_idx[r * 3 + 1] = outi[1]; g_idx[r * 3 + 2] = outi[2];
    g_w[r * 3 + 0] = r0 / s; g_w[r * 3 + 1] = r1 / s; g_w[r * 3 + 2] = r2 / s;
}

// ---------------- 2) build x1 = fp16([points1 | interp(points2)]) -----------
__global__ void __launch_bounds__(256) prep_x1_kernel(const float* __restrict__ points1,
                                                      const float* __restrict__ P2) {
    const int idx = blockIdx.x * 256 + threadIdx.x;
    const int row = idx / 48;
    const int g8  = (idx % 48) * 8;
    __half2 out[4];
    if (g8 < C1) {
        const float* src = points1 + (size_t)row * C1 + g8;
        float4 f0 = *(const float4*)(src);
        float4 f1 = *(const float4*)(src + 4);
        out[0] = __floats2half2_rn(f0.x, f0.y);
        out[1] = __floats2half2_rn(f0.z, f0.w);
        out[2] = __floats2half2_rn(f1.x, f1.y);
        out[3] = __floats2half2_rn(f1.z, f1.w);
    } else {
        const int cc = g8 - C1;
        const float* p2b = P2 + (size_t)(row >> 13) * MPTS * C2;   // row / NPTS
        const float w0 = g_w[row * 3 + 0], w1 = g_w[row * 3 + 1], w2 = g_w[row * 3 + 2];
        const float* q0 = p2b + (size_t)g_idx[row * 3 + 0] * C2 + cc;
        const float* q1 = p2b + (size_t)g_idx[row * 3 + 1] * C2 + cc;
        const float* q2 = p2b + (size_t)g_idx[row * 3 + 2] * C2 + cc;
        #pragma unroll
        for (int h = 0; h < 2; h++) {
            float4 a = *(const float4*)(q0 + 4 * h);
            float4 b = *(const float4*)(q1 + 4 * h);
            float4 d = *(const float4*)(q2 + 4 * h);
            float v0 = a.x * w0 + b.x * w1 + d.x * w2;
            float v1 = a.y * w0 + b.y * w1 + d.y * w2;
            float v2 = a.z * w0 + b.z * w1 + d.z * w2;
            float v3 = a.w * w0 + b.w * w1 + d.w * w2;
            out[2 * h + 0] = __floats2half2_rn(v0, v1);
            out[2 * h + 1] = __floats2half2_rn(v2, v3);
        }
    }
    *(uint4*)(g_x1 + (size_t)row * CIN + g8) = *(uint4*)out;
}

// ---------------- 3) build x2 = fp16(relu(bn(y1))) --------------------------
__global__ void __launch_bounds__(256) prep_x2_kernel() {
    __shared__ float sA[HDIM], sC[HDIM];
    sA[threadIdx.x] = g_a[threadIdx.x];
    sC[threadIdx.x] = g_c[threadIdx.x];
    __syncthreads();
    const int idx = blockIdx.x * 256 + threadIdx.x;
    const int row = idx / 32;
    const int c8  = (idx % 32) * 8;
    const float* src = g_y1 + (size_t)row * HDIM + c8;
    float4 f0 = *(const float4*)(src);
    float4 f1 = *(const float4*)(src + 4);
    __half2 out[4];
    out[0] = __floats2half2_rn(fmaxf(f0.x * sA[c8+0] + sC[c8+0], 0.f),
                               fmaxf(f0.y * sA[c8+1] + sC[c8+1], 0.f));
    out[1] = __floats2half2_rn(fmaxf(f0.z * sA[c8+2] + sC[c8+2], 0.f),
                               fmaxf(f0.w * sA[c8+3] + sC[c8+3], 0.f));
    out[2] = __floats2half2_rn(fmaxf(f1.x * sA[c8+4] + sC[c8+4], 0.f),
                               fmaxf(f1.y * sA[c8+5] + sC[c8+5], 0.f));
    out[3] = __floats2half2_rn(fmaxf(f1.z * sA[c8+6] + sC[c8+6], 0.f),
                               fmaxf(f1.w * sA[c8+7] + sC[c8+7], 0.f));
    *(uint4*)(g_x2 + (size_t)row * HDIM + c8) = *(uint4*)out;
}

// ---------------- 4) streaming FP16 HMMA GEMM  C = A * W^T + bias -----------
// CTA tile 128(M) x 128(N), 256 threads / 8 warps (2 row-groups x 4 col-groups,
// warp tile 64x32 as in the proven R8 kernel), KC=64, 2 cp.async stages,
// 2 CTAs/SM. Balanced L2 traffic: W*(M/128) + A*(N/128).
// grid = (ROWS/128, HDIM/128)
#define PITCHB    144                      // bytes per row (72 halves)
#define OFF_BIAS  0
#define OFF_T     1024
#define A_SZ      (128 * PITCHB)           // 18432
#define B_SZ      (128 * PITCHB)           // 18432
#define STG_SZ    (A_SZ + B_SZ)            // 36864
#define OFF_A(s)  (OFF_T + (s) * STG_SZ)
#define OFF_B(s)  (OFF_A(s) + A_SZ)
#define SMEM_SZ   (OFF_T + 2 * STG_SZ)     // 74752 -> 2 CTAs/SM

template <int K>
__global__ void __launch_bounds__(256, 2) gemm_f16(const __half* __restrict__ Ah,
                                                   const __half* __restrict__ WH,
                                                   const float* __restrict__ bias,
                                                   float* __restrict__ dst_) {
    constexpr int NC = K / KC;
    extern __shared__ char smem[];
    const uint32_t sb = smem_u32(smem);
    const int tid = threadIdx.x, wid = tid >> 5, lane = tid & 31;
    const int rowBase = blockIdx.x * 128;
    const int nBase   = blockIdx.y * 128;

    float* sBias = (float*)(smem + OFF_BIAS);
    if (tid < 128) sBias[tid] = bias[nBase + tid];
    __syncthreads();

    auto fillB = [&](int c, int s) {
        const int kt = c * KC;
        const uint32_t base = sb + OFF_B(s);
        #pragma unroll
        for (int it = 0; it < 4; it++) {
            const int idx = tid + 256 * it;       // 0..1023
            const int n = idx >> 3, j = idx & 7;  // local W row, 16B chunk
            cpa16(base + (uint32_t)(n * PITCHB + j * 16),
                  WH + (size_t)(nBase + n) * K + kt + j * 8);
        }
    };
    auto fillA = [&](int c, int s) {
        const int kt = c * KC;
        const uint32_t base = sb + OFF_A(s);
        #pragma unroll
        for (int it = 0; it < 4; it++) {
            const int idx = tid + 256 * it;       // 0..1023
            const int n = idx >> 3, j = idx & 7;  // tile row, 16B chunk
            cpa16(base + (uint32_t)(n * PITCHB + j * 16),
                  Ah + (size_t)(rowBase + n) * K + kt + j * 8);
        }
    };

    // ---- warp layout: 2 row-groups (64 rows) x 4 col-groups (32 cols)
    const int rh = wid >> 2;          // row group
    const int cg = wid & 3;           // col group
    const int nb = cg * 32;

    // ---- accumulators init = bias (folded epilogue add)
    float acc[4][4][4];
    #pragma unroll
    for (int nt = 0; nt < 4; nt++) {
        const float b0 = sBias[nb + nt * 8 + 2 * (lane & 3)];
        const float b1 = sBias[nb + nt * 8 + 2 * (lane & 3) + 1];
        #pragma unroll
        for (int mt = 0; mt < 4; mt++) {
            acc[mt][nt][0] = b0; acc[mt][nt][1] = b1;
            acc[mt][nt][2] = b0; acc[mt][nt][3] = b1;
        }
    }

    // ldmatrix per-lane address parts (proven R8 mapping)
    const uint32_t aRow = (uint32_t)(((lane >> 3) & 1) * 8 + (lane & 7));
    const uint32_t aK   = (uint32_t)((lane >> 4) * 8);
    const uint32_t bRow = (uint32_t)((lane >> 4) * 8 + (lane & 7));
    const uint32_t bK   = (uint32_t)(((lane >> 3) & 1) * 8);

    // ---- prologue
    fillA(0, 0); fillB(0, 0); CP_COMMIT();

    #pragma unroll 1
    for (int c = 0; c < NC; c++) {
        const int s = c & 1;
        if (c + 1 < NC) {
            fillA(c + 1, 1 - s); fillB(c + 1, 1 - s); CP_COMMIT();
            CP_WAIT1();
        } else {
            CP_WAIT0();
        }
        __syncthreads();

        const uint32_t baseA = sb + OFF_A(0) + (uint32_t)s * STG_SZ;
        const uint32_t baseB = baseA + A_SZ;

        #pragma unroll
        for (int kk = 0; kk < 4; kk++) {
            uint32_t a[4][4], bh[8];
            #pragma unroll
            for (int mt = 0; mt < 4; mt++)
                ldsm4(a[mt], baseA + (rh * 64 + mt * 16 + aRow) * PITCHB + (kk * 16 + aK) * 2);
            #pragma unroll
            for (int j2 = 0; j2 < 2; j2++)
                ldsm4(&bh[j2 * 4], baseB + (nb + j2 * 16 + bRow) * PITCHB + (kk * 16 + bK) * 2);
            #pragma unroll
            for (int mt = 0; mt < 4; mt++)
                #pragma unroll
                for (int nt = 0; nt < 4; nt++)
                    mma_f16(acc[mt][nt], a[mt], &bh[nt * 2]);
        }
        __syncthreads();
    }

    // ---- epilogue 1: per-(m-tile,row-group) BN partials (transposed)
    {
        const int part = blockIdx.x * 2 + rh;
        #pragma unroll
        for (int nt = 0; nt < 4; nt++) {
            float s0 = 0.f, s1 = 0.f, q0 = 0.f, q1 = 0.f;
            #pragma unroll
            for (int mt = 0; mt < 4; mt++) {
                float v0 = acc[mt][nt][0], v1 = acc[mt][nt][1];
                float v2 = acc[mt][nt][2], v3 = acc[mt][nt][3];
                s0 += v0 + v2;  s1 += v1 + v3;
                q0 += v0 * v0 + v2 * v2;  q1 += v1 * v1 + v3 * v3;
            }
            #pragma unroll
            for (int o = 4; o < 32; o <<= 1) {
                s0 += __shfl_xor_sync(0xffffffffu, s0, o);
                s1 += __shfl_xor_sync(0xffffffffu, s1, o);
                q0 += __shfl_xor_sync(0xffffffffu, q0, o);
                q1 += __shfl_xor_sync(0xffffffffu, q1, o);
            }
            if (lane < 4) {
                const int col = nBase + nb + nt * 8 + 2 * lane;
                g_psum[(size_t)col * NPART + part]       = s0;
                g_psum[(size_t)(col + 1) * NPART + part] = s1;
                g_psq[(size_t)col * NPART + part]        = q0;
                g_psq[(size_t)(col + 1) * NPART + part]  = q1;
            }
        }
    }

    // ---- epilogue 2: store fp32 y
    #pragma unroll
    for (int mt = 0; mt < 4; mt++) {
        const int row = rowBase + rh * 64 + mt * 16 + (lane >> 2);
        #pragma unroll
        for (int nt = 0; nt < 4; nt++) {
            const int col = nBase + nb + nt * 8 + 2 * (lane & 3);
            float2 v0 = {acc[mt][nt][0], acc[mt][nt][1]};
            float2 v1 = {acc[mt][nt][2], acc[mt][nt][3]};
            *(float2*)(dst_ + (size_t)row * HDIM + col)       = v0;
            *(float2*)(dst_ + (size_t)(row + 8) * HDIM + col) = v1;
        }
    }
}

// ---------------- 5) BN stats final reduce (one block per channel) ----------
__global__ void __launch_bounds__(256) stats_final_kernel(const float* __restrict__ gamma,
                                                          const float* __restrict__ beta) {
    const int ch = blockIdx.x;
    const int t  = threadIdx.x;
    const float* ps = g_psum + (size_t)ch * NPART;
    const float* pq = g_psq + (size_t)ch * NPART;
    float s = 0.f, q = 0.f;
    #pragma unroll
    for (int k = 0; k < NPART / 256; k++) {
        s += ps[t + 256 * k];
        q += pq[t + 256 * k];
    }
    __shared__ float ss[256], sq[256];
    ss[t] = s; sq[t] = q;
    __syncthreads();
    #pragma unroll
    for (int o = 128; o >= 32; o >>= 1) {
        if (t < o) { ss[t] += ss[t + o]; sq[t] += sq[t + o]; }
        __syncthreads();
    }
    if (t < 32) {
        s = ss[t]; q = sq[t];
        #pragma unroll
        for (int o = 16; o > 0; o >>= 1) {
            s += __shfl_xor_sync(0xffffffffu, s, o);
            q += __shfl_xor_sync(0xffffffffu, q, o);
        }
        if (t == 0) {
            const float mean = s * (1.f / (float)ROWS);
            const float var  = q * (1.f / (float)ROWS) - mean * mean;
            const float a    = gamma[ch] * rsqrtf(var + 1e-5f);
            g_a[ch] = a;
            g_c[ch] = beta[ch] - mean * a;
        }
    }
}

// ---------------- 6) in-place bn+relu on d_out ------------------------------
__global__ void __launch_bounds__(256) bnrelu_kernel(float* __restrict__ out) {
    size_t i = (size_t)blockIdx.x * 256 + threadIdx.x;   // float4 index
    float4* o4 = (float4*)out;
    float4 v = o4[i];
    int c = (int)((i << 2) & (HDIM - 1));
    v.x = fmaxf(v.x * g_a[c + 0] + g_c[c + 0], 0.f);
    v.y = fmaxf(v.y * g_a[c + 1] + g_c[c + 1], 0.f);
    v.z = fmaxf(v.z * g_a[c + 2] + g_c[c + 2], 0.f);
    v.w = fmaxf(v.w * g_a[c + 3] + g_c[c + 3], 0.f);
    o4[i] = v;
}

// ---------------- host ------------------------------------------------------
extern "C" void kernel_launch(void* const* d_in, const int* in_sizes, int n_in,
                              void* d_out, int out_size) {
    const float* xyz1    = (const float*)d_in[0];
    const float* xyz2    = (const float*)d_in[1];
    const float* points1 = (const float*)d_in[2];
    const float* points2 = (const float*)d_in[3];
    const float* W1      = (const float*)d_in[4];
    const float* b1      = (const float*)d_in[5];
    const float* gamma1  = (const float*)d_in[6];
    const float* beta1   = (const float*)d_in[7];
    const float* W2      = (const float*)d_in[8];
    const float* b2      = (const float*)d_in[9];
    const float* gamma2  = (const float*)d_in[10];
    const float* beta2   = (const float*)d_in[11];
    float* out = (float*)d_out;

    cudaFuncSetAttribute(gemm_f16<CIN>,  cudaFuncAttributeMaxDynamicSharedMemorySize, SMEM_SZ);
    cudaFuncSetAttribute(gemm_f16<HDIM>, cudaFuncAttributeMaxDynamicSharedMemorySize, SMEM_SZ);

    __half *x1p = nullptr, *x2p = nullptr, *w1p = nullptr, *w2p = nullptr;
    float *y1p = nullptr;
    cudaGetSymbolAddress((void**)&x1p, g_x1);
    cudaGetSymbolAddress((void**)&x2p, g_x2);
    cudaGetSymbolAddress((void**)&w1p, g_w1h);
    cudaGetSymbolAddress((void**)&w2p, g_w2h);
    cudaGetSymbolAddress((void**)&y1p, g_y1);

    prep_w_kernel<<<(256 * 384) / 256, 256>>>(W1, W2);
    knn_kernel<<<BB * (NPTS / 256), 256>>>(xyz1, xyz2);
    prep_x1_kernel<<<(ROWS * 48) / 256, 256>>>(points1, points2);

    gemm_f16<CIN><<<dim3(ROWS / 128, HDIM / 128), 256, SMEM_SZ>>>(x1p, w1p, b1, y1p);
    stats_final_kernel<<<HDIM, 256>>>(gamma1, beta1);
    prep_x2_kernel<<<(ROWS * 32) / 256, 256>>>();

    gemm_f16<HDIM><<<dim3(ROWS / 128, HDIM / 128), 256, SMEM_SZ>>>(x2p, w2p, b2, out);
    stats_final_kernel<<<HDIM, 256>>>(gamma2, beta2);

    bnrelu_kernel<<<(ROWS * HDIM / 4) / 256, 256>>>(out);
}

// round 12
// speedup vs baseline: 1.0880x; 1.0061x over previous
#include <cuda_runtime.h>
#include <cuda_fp16.h>
#include <cstdint>
#include <math.h>

// Problem constants (FP_Layer: B=8, N=8192, M=2048, C1=128, C2=256, H=256)
#define BB    8
#define NPTS  8192
#define MPTS  2048
#define C1    128
#define C2    256
#define HDIM  256
#define CIN   384
#define ROWS  (BB * NPTS)      // 65536
#define NPART 1024             // 512 m-tiles * 2 row-groups
#define KC    64               // K-chunk per stage

// ---------------- scratch (device globals; no allocation allowed) ----------
__device__ float g_y1[(size_t)ROWS * HDIM];                 // 64 MB fp32
__device__ __align__(16) __half g_x1[(size_t)ROWS * CIN];   // 48 MB fp16
__device__ __align__(16) __half g_x2[(size_t)ROWS * HDIM];  // 32 MB fp16
__device__ int   g_idx[ROWS * 3];
__device__ float g_w[ROWS * 3];
__device__ float g_psum[HDIM * NPART];          // [col][part] transposed
__device__ float g_psq[HDIM * NPART];
__device__ float g_a[HDIM];
__device__ float g_c[HDIM];
__device__ __align__(16) __half g_w1h[256 * 384];
__device__ __align__(16) __half g_w2h[256 * 256];

// ================= PTX helpers (baseline ISA, OK on compute_103) ============
__device__ __forceinline__ uint32_t smem_u32(const void* p) {
    uint32_t a;
    asm("{ .reg .u64 t; cvta.to.shared.u64 t, %1; cvt.u32.u64 %0, t; }" : "=r"(a) : "l"(p));
    return a;
}
__device__ __forceinline__ void cpa16(uint32_t s, const void* g) {
    asm volatile("cp.async.cg.shared.global [%0], [%1], 16;" :: "r"(s), "l"(g));
}
#define CP_COMMIT() asm volatile("cp.async.commit_group;" ::: "memory")
#define CP_WAIT2()  asm volatile("cp.async.wait_group 2;" ::: "memory")
#define CP_WAIT1()  asm volatile("cp.async.wait_group 1;" ::: "memory")
#define CP_WAIT0()  asm volatile("cp.async.wait_group 0;" ::: "memory")

__device__ __forceinline__ void ldsm4(uint32_t* r, uint32_t addr) {
    asm volatile("ldmatrix.sync.aligned.m8n8.x4.shared.b16 {%0,%1,%2,%3}, [%4];"
                 : "=r"(r[0]), "=r"(r[1]), "=r"(r[2]), "=r"(r[3]) : "r"(addr));
}
__device__ __forceinline__ void mma_f16(float* c, const uint32_t* a, const uint32_t* b) {
    asm volatile(
        "mma.sync.aligned.m16n8k16.row.col.f32.f16.f16.f32 "
        "{%0,%1,%2,%3}, {%4,%5,%6,%7}, {%8,%9}, {%0,%1,%2,%3};"
        : "+f"(c[0]), "+f"(c[1]), "+f"(c[2]), "+f"(c[3])
        : "r"(a[0]), "r"(a[1]), "r"(a[2]), "r"(a[3]), "r"(b[0]), "r"(b[1]));
}

// ---------------- 0) convert W to fp16 --------------------------------------
__global__ void __launch_bounds__(256) prep_w_kernel(const float* __restrict__ W1,
                                                     const float* __restrict__ W2) {
    int i = blockIdx.x * 256 + threadIdx.x;   // grid covers 256*384
    g_w1h[i] = __float2half_rn(W1[i]);
    if (i < 256 * 256) g_w2h[i] = __float2half_rn(W2[i]);
}

// ---------------- 1) 3-NN over xyz2 (4 independent compare chains) ---------
__global__ void __launch_bounds__(256) knn_kernel(const float* __restrict__ xyz1,
                                                  const float* __restrict__ xyz2) {
    __shared__ float4 s2[MPTS];               // x,y,z,|.|^2  (32KB)
    int b    = blockIdx.x >> 5;
    int tile = blockIdx.x & 31;
    const float* x2 = xyz2 + (size_t)b * MPTS * 3;
    for (int i = threadIdx.x; i < MPTS; i += 256) {
        float x = x2[i * 3 + 0], y = x2[i * 3 + 1], z = x2[i * 3 + 2];
        s2[i] = make_float4(x, y, z, x * x + y * y + z * z);
    }
    __syncthreads();

    int n = tile * 256 + threadIdx.x;
    int r = b * NPTS + n;
    float px = xyz1[(size_t)r * 3 + 0];
    float py = xyz1[(size_t)r * 3 + 1];
    float pz = xyz1[(size_t)r * 3 + 2];
    float pn = px * px + py * py + pz * pz;

    float cd[4][3];
    int   ci[4][3];
    #pragma unroll
    for (int j = 0; j < 4; j++) {
        cd[j][0] = cd[j][1] = cd[j][2] = 3.4e38f;
        ci[j][0] = ci[j][1] = ci[j][2] = 0;
    }
    for (int m = 0; m < MPTS; m += 4) {
        #pragma unroll
        for (int j = 0; j < 4; j++) {
            float4 t = s2[m + j];
            // identical formula to reference: |a|^2 + |b|^2 - 2 a.b
            float d = (pn + t.w) - 2.f * (px * t.x + py * t.y + pz * t.z);
            if (d < cd[j][2]) {
                if (d < cd[j][1]) {
                    cd[j][2] = cd[j][1]; ci[j][2] = ci[j][1];
                    if (d < cd[j][0]) {
                        cd[j][1] = cd[j][0]; ci[j][1] = ci[j][0];
                        cd[j][0] = d; ci[j][0] = m + j;
                    } else { cd[j][1] = d; ci[j][1] = m + j; }
                } else { cd[j][2] = d; ci[j][2] = m + j; }
            }
        }
    }
    // exact lexicographic (d, idx) merge of 12 candidates -> 3 smallest
    float md[12]; int mi[12];
    #pragma unroll
    for (int j = 0; j < 4; j++)
        #pragma unroll
        for (int k = 0; k < 3; k++) { md[j * 3 + k] = cd[j][k]; mi[j * 3 + k] = ci[j][k]; }
    float outd[3]; int outi[3];
    #pragma unroll
    for (int s = 0; s < 3; s++) {
        float bd = 3.5e38f; int bi = 0x7fffffff; int bk = 0;
        #pragma unroll
        for (int k = 0; k < 12; k++) {
            bool take = (md[k] < bd) || (md[k] == bd && mi[k] < bi);
            if (take) { bd = md[k]; bi = mi[k]; bk = k; }
        }
        outd[s] = bd; outi[s] = bi;
        md[bk] = 3.5e38f; mi[bk] = 0x7fffffff;
    }
    float r0 = 1.f / (outd[0] + 1e-8f);
    float r1 = 1.f / (outd[1] + 1e-8f);
    float r2 = 1.f / (outd[2] + 1e-8f);
    float s  = (r0 + r1) + r2;
    g_idx[r * 3 + 0] = outi[0]; g_idx[r * 3 + 1] = outi[1]; g_idx[r * 3 + 2] = outi[2];
    g_w[r * 3 + 0] = r0 / s; g_w[r * 3 + 1] = r1 / s; g_w[r * 3 + 2] = r2 / s;
}

// ---------------- 2) build x1 = fp16([points1 | interp(points2)]) -----------
__global__ void __launch_bounds__(256) prep_x1_kernel(const float* __restrict__ points1,
                                                      const float* __restrict__ P2) {
    const int idx = blockIdx.x * 256 + threadIdx.x;
    const int row = idx / 48;
    const int g8  = (idx % 48) * 8;
    __half2 out[4];
    if (g8 < C1) {
        const float* src = points1 + (size_t)row * C1 + g8;
        float4 f0 = *(const float4*)(src);
        float4 f1 = *(const float4*)(src + 4);
        out[0] = __floats2half2_rn(f0.x, f0.y);
        out[1] = __floats2half2_rn(f0.z, f0.w);
        out[2] = __floats2half2_rn(f1.x, f1.y);
        out[3] = __floats2half2_rn(f1.z, f1.w);
    } else {
        const int cc = g8 - C1;
        const float* p2b = P2 + (size_t)(row >> 13) * MPTS * C2;   // row / NPTS
        const float w0 = g_w[row * 3 + 0], w1 = g_w[row * 3 + 1], w2 = g_w[row * 3 + 2];
        const float* q0 = p2b + (size_t)g_idx[row * 3 + 0] * C2 + cc;
        const float* q1 = p2b + (size_t)g_idx[row * 3 + 1] * C2 + cc;
        const float* q2 = p2b + (size_t)g_idx[row * 3 + 2] * C2 + cc;
        #pragma unroll
        for (int h = 0; h < 2; h++) {
            float4 a = *(const float4*)(q0 + 4 * h);
            float4 b = *(const float4*)(q1 + 4 * h);
            float4 d = *(const float4*)(q2 + 4 * h);
            float v0 = a.x * w0 + b.x * w1 + d.x * w2;
            float v1 = a.y * w0 + b.y * w1 + d.y * w2;
            float v2 = a.z * w0 + b.z * w1 + d.z * w2;
            float v3 = a.w * w0 + b.w * w1 + d.w * w2;
            out[2 * h + 0] = __floats2half2_rn(v0, v1);
            out[2 * h + 1] = __floats2half2_rn(v2, v3);
        }
    }
    *(uint4*)(g_x1 + (size_t)row * CIN + g8) = *(uint4*)out;
}

// ---------------- 3) build x2 = fp16(relu(bn(y1))) --------------------------
__global__ void __launch_bounds__(256) prep_x2_kernel() {
    __shared__ float sA[HDIM], sC[HDIM];
    sA[threadIdx.x] = g_a[threadIdx.x];
    sC[threadIdx.x] = g_c[threadIdx.x];
    __syncthreads();
    const int idx = blockIdx.x * 256 + threadIdx.x;
    const int row = idx / 32;
    const int c8  = (idx % 32) * 8;
    const float* src = g_y1 + (size_t)row * HDIM + c8;
    float4 f0 = *(const float4*)(src);
    float4 f1 = *(const float4*)(src + 4);
    __half2 out[4];
    out[0] = __floats2half2_rn(fmaxf(f0.x * sA[c8+0] + sC[c8+0], 0.f),
                               fmaxf(f0.y * sA[c8+1] + sC[c8+1], 0.f));
    out[1] = __floats2half2_rn(fmaxf(f0.z * sA[c8+2] + sC[c8+2], 0.f),
                               fmaxf(f0.w * sA[c8+3] + sC[c8+3], 0.f));
    out[2] = __floats2half2_rn(fmaxf(f1.x * sA[c8+4] + sC[c8+4], 0.f),
                               fmaxf(f1.y * sA[c8+5] + sC[c8+5], 0.f));
    out[3] = __floats2half2_rn(fmaxf(f1.z * sA[c8+6] + sC[c8+6], 0.f),
                               fmaxf(f1.w * sA[c8+7] + sC[c8+7], 0.f));
    *(uint4*)(g_x2 + (size_t)row * HDIM + c8) = *(uint4*)out;
}

// ---------------- 4) streaming FP16 HMMA GEMM  C = A * W^T + bias -----------
// CTA tile 128(M) x 128(N), 256 threads / 8 warps (2 row-groups x 4 col-groups,
// warp tile 64x32), KC=64, *** 3-stage cp.async ring (2-chunk lookahead) ***,
// 2 CTAs/SM (111.6KB smem each). grid = (ROWS/128, HDIM/128)
#define PITCHB    144                      // bytes per row (72 halves)
#define OFF_BIAS  0
#define OFF_T     1024
#define A_SZ      (128 * PITCHB)           // 18432
#define B_SZ      (128 * PITCHB)           // 18432
#define STG_SZ    (A_SZ + B_SZ)            // 36864
#define OFF_A(s)  (OFF_T + (s) * STG_SZ)
#define OFF_B(s)  (OFF_A(s) + A_SZ)
#define SMEM_SZ   (OFF_T + 3 * STG_SZ)     // 111616 -> 2 CTAs/SM (223.2KB)

template <int K>
__global__ void __launch_bounds__(256, 2) gemm_f16(const __half* __restrict__ Ah,
                                                   const __half* __restrict__ WH,
                                                   const float* __restrict__ bias,
                                                   float* __restrict__ dst_) {
    constexpr int NC = K / KC;
    extern __shared__ char smem[];
    const uint32_t sb = smem_u32(smem);
    const int tid = threadIdx.x, wid = tid >> 5, lane = tid & 31;
    const int rowBase = blockIdx.x * 128;
    const int nBase   = blockIdx.y * 128;

    float* sBias = (float*)(smem + OFF_BIAS);
    if (tid < 128) sBias[tid] = bias[nBase + tid];
    __syncthreads();

    auto fillB = [&](int c, int s) {
        const int kt = c * KC;
        const uint32_t base = sb + OFF_B(s);
        #pragma unroll
        for (int it = 0; it < 4; it++) {
            const int idx = tid + 256 * it;       // 0..1023
            const int n = idx >> 3, j = idx & 7;  // local W row, 16B chunk
            cpa16(base + (uint32_t)(n * PITCHB + j * 16),
                  WH + (size_t)(nBase + n) * K + kt + j * 8);
        }
    };
    auto fillA = [&](int c, int s) {
        const int kt = c * KC;
        const uint32_t base = sb + OFF_A(s);
        #pragma unroll
        for (int it = 0; it < 4; it++) {
            const int idx = tid + 256 * it;       // 0..1023
            const int n = idx >> 3, j = idx & 7;  // tile row, 16B chunk
            cpa16(base + (uint32_t)(n * PITCHB + j * 16),
                  Ah + (size_t)(rowBase + n) * K + kt + j * 8);
        }
    };

    // ---- warp layout: 2 row-groups (64 rows) x 4 col-groups (32 cols)
    const int rh = wid >> 2;          // row group
    const int cg = wid & 3;           // col group
    const int nb = cg * 32;

    // ---- accumulators init = bias (folded epilogue add)
    float acc[4][4][4];
    #pragma unroll
    for (int nt = 0; nt < 4; nt++) {
        const float b0 = sBias[nb + nt * 8 + 2 * (lane & 3)];
        const float b1 = sBias[nb + nt * 8 + 2 * (lane & 3) + 1];
        #pragma unroll
        for (int mt = 0; mt < 4; mt++) {
            acc[mt][nt][0] = b0; acc[mt][nt][1] = b1;
            acc[mt][nt][2] = b0; acc[mt][nt][3] = b1;
        }
    }

    // ldmatrix per-lane address parts (proven R8 mapping)
    const uint32_t aRow = (uint32_t)(((lane >> 3) & 1) * 8 + (lane & 7));
    const uint32_t aK   = (uint32_t)((lane >> 4) * 8);
    const uint32_t bRow = (uint32_t)((lane >> 4) * 8 + (lane & 7));
    const uint32_t bK   = (uint32_t)(((lane >> 3) & 1) * 8);

    // ---- prologue: stages 0,1 in flight (2-chunk lookahead)
    fillA(0, 0); fillB(0, 0); CP_COMMIT();
    fillA(1, 1); fillB(1, 1); CP_COMMIT();

    #pragma unroll 1
    for (int c = 0; c < NC; c++) {
        const int s = c % 3;
        if (c > 0) __syncthreads();             // readers done with stage (c+2)%3
        if (c + 2 < NC) {
            const int s2 = (c + 2) % 3;
            fillA(c + 2, s2); fillB(c + 2, s2); CP_COMMIT();
            CP_WAIT2();
        } else if (c + 1 < NC) {
            CP_WAIT1();
        } else {
            CP_WAIT0();
        }
        __syncthreads();                        // stage c visible to all

        const uint32_t baseA = sb + OFF_A(0) + (uint32_t)s * STG_SZ;
        const uint32_t baseB = baseA + A_SZ;

        #pragma unroll
        for (int kk = 0; kk < 4; kk++) {
            uint32_t a[4][4], bh[8];
            #pragma unroll
            for (int mt = 0; mt < 4; mt++)
                ldsm4(a[mt], baseA + (rh * 64 + mt * 16 + aRow) * PITCHB + (kk * 16 + aK) * 2);
            #pragma unroll
            for (int j2 = 0; j2 < 2; j2++)
                ldsm4(&bh[j2 * 4], baseB + (nb + j2 * 16 + bRow) * PITCHB + (kk * 16 + bK) * 2);
            #pragma unroll
            for (int mt = 0; mt < 4; mt++)
                #pragma unroll
                for (int nt = 0; nt < 4; nt++)
                    mma_f16(acc[mt][nt], a[mt], &bh[nt * 2]);
        }
    }

    // ---- epilogue 1: per-(m-tile,row-group) BN partials (transposed)
    {
        const int part = blockIdx.x * 2 + rh;
        #pragma unroll
        for (int nt = 0; nt < 4; nt++) {
            float s0 = 0.f, s1 = 0.f, q0 = 0.f, q1 = 0.f;
            #pragma unroll
            for (int mt = 0; mt < 4; mt++) {
                float v0 = acc[mt][nt][0], v1 = acc[mt][nt][1];
                float v2 = acc[mt][nt][2], v3 = acc[mt][nt][3];
                s0 += v0 + v2;  s1 += v1 + v3;
                q0 += v0 * v0 + v2 * v2;  q1 += v1 * v1 + v3 * v3;
            }
            #pragma unroll
            for (int o = 4; o < 32; o <<= 1) {
                s0 += __shfl_xor_sync(0xffffffffu, s0, o);
                s1 += __shfl_xor_sync(0xffffffffu, s1, o);
                q0 += __shfl_xor_sync(0xffffffffu, q0, o);
                q1 += __shfl_xor_sync(0xffffffffu, q1, o);
            }
            if (lane < 4) {
                const int col = nBase + nb + nt * 8 + 2 * lane;
                g_psum[(size_t)col * NPART + part]       = s0;
                g_psum[(size_t)(col + 1) * NPART + part] = s1;
                g_psq[(size_t)col * NPART + part]        = q0;
                g_psq[(size_t)(col + 1) * NPART + part]  = q1;
            }
        }
    }

    // ---- epilogue 2: store fp32 y
    #pragma unroll
    for (int mt = 0; mt < 4; mt++) {
        const int row = rowBase + rh * 64 + mt * 16 + (lane >> 2);
        #pragma unroll
        for (int nt = 0; nt < 4; nt++) {
            const int col = nBase + nb + nt * 8 + 2 * (lane & 3);
            float2 v0 = {acc[mt][nt][0], acc[mt][nt][1]};
            float2 v1 = {acc[mt][nt][2], acc[mt][nt][3]};
            *(float2*)(dst_ + (size_t)row * HDIM + col)       = v0;
            *(float2*)(dst_ + (size_t)(row + 8) * HDIM + col) = v1;
        }
    }
}

// ---------------- 5) BN stats final reduce (one block per channel) ----------
__global__ void __launch_bounds__(256) stats_final_kernel(const float* __restrict__ gamma,
                                                          const float* __restrict__ beta) {
    const int ch = blockIdx.x;
    const int t  = threadIdx.x;
    const float* ps = g_psum + (size_t)ch * NPART;
    const float* pq = g_psq + (size_t)ch * NPART;
    float s = 0.f, q = 0.f;
    #pragma unroll
    for (int k = 0; k < NPART / 256; k++) {
        s += ps[t + 256 * k];
        q += pq[t + 256 * k];
    }
    __shared__ float ss[256], sq[256];
    ss[t] = s; sq[t] = q;
    __syncthreads();
    #pragma unroll
    for (int o = 128; o >= 32; o >>= 1) {
        if (t < o) { ss[t] += ss[t + o]; sq[t] += sq[t + o]; }
        __syncthreads();
    }
    if (t < 32) {
        s = ss[t]; q = sq[t];
        #pragma unroll
        for (int o = 16; o > 0; o >>= 1) {
            s += __shfl_xor_sync(0xffffffffu, s, o);
            q += __shfl_xor_sync(0xffffffffu, q, o);
        }
        if (t == 0) {
            const float mean = s * (1.f / (float)ROWS);
            const float var  = q * (1.f / (float)ROWS) - mean * mean;
            const float a    = gamma[ch] * rsqrtf(var + 1e-5f);
            g_a[ch] = a;
            g_c[ch] = beta[ch] - mean * a;
        }
    }
}

// ---------------- 6) in-place bn+relu on d_out ------------------------------
__global__ void __launch_bounds__(256) bnrelu_kernel(float* __restrict__ out) {
    size_t i = (size_t)blockIdx.x * 256 + threadIdx.x;   // float4 index
    float4* o4 = (float4*)out;
    float4 v = o4[i];
    int c = (int)((i << 2) & (HDIM - 1));
    v.x = fmaxf(v.x * g_a[c + 0] + g_c[c + 0], 0.f);
    v.y = fmaxf(v.y * g_a[c + 1] + g_c[c + 1], 0.f);
    v.z = fmaxf(v.z * g_a[c + 2] + g_c[c + 2], 0.f);
    v.w = fmaxf(v.w * g_a[c + 3] + g_c[c + 3], 0.f);
    o4[i] = v;
}

// ---------------- host ------------------------------------------------------
extern "C" void kernel_launch(void* const* d_in, const int* in_sizes, int n_in,
                              void* d_out, int out_size) {
    const float* xyz1    = (const float*)d_in[0];
    const float* xyz2    = (const float*)d_in[1];
    const float* points1 = (const float*)d_in[2];
    const float* points2 = (const float*)d_in[3];
    const float* W1      = (const float*)d_in[4];
    const float* b1      = (const float*)d_in[5];
    const float* gamma1  = (const float*)d_in[6];
    const float* beta1   = (const float*)d_in[7];
    const float* W2      = (const float*)d_in[8];
    const float* b2      = (const float*)d_in[9];
    const float* gamma2  = (const float*)d_in[10];
    const float* beta2   = (const float*)d_in[11];
    float* out = (float*)d_out;

    cudaFuncSetAttribute(gemm_f16<CIN>,  cudaFuncAttributeMaxDynamicSharedMemorySize, SMEM_SZ);
    cudaFuncSetAttribute(gemm_f16<HDIM>, cudaFuncAttributeMaxDynamicSharedMemorySize, SMEM_SZ);

    __half *x1p = nullptr, *x2p = nullptr, *w1p = nullptr, *w2p = nullptr;
    float *y1p = nullptr;
    cudaGetSymbolAddress((void**)&x1p, g_x1);
    cudaGetSymbolAddress((void**)&x2p, g_x2);
    cudaGetSymbolAddress((void**)&w1p, g_w1h);
    cudaGetSymbolAddress((void**)&w2p, g_w2h);
    cudaGetSymbolAddress((void**)&y1p, g_y1);

    prep_w_kernel<<<(256 * 384) / 256, 256>>>(W1, W2);
    knn_kernel<<<BB * (NPTS / 256), 256>>>(xyz1, xyz2);
    prep_x1_kernel<<<(ROWS * 48) / 256, 256>>>(points1, points2);

    gemm_f16<CIN><<<dim3(ROWS / 128, HDIM / 128), 256, SMEM_SZ>>>(x1p, w1p, b1, y1p);
    stats_final_kernel<<<HDIM, 256>>>(gamma1, beta1);
    prep_x2_kernel<<<(ROWS * 32) / 256, 256>>>();

    gemm_f16<HDIM><<<dim3(ROWS / 128, HDIM / 128), 256, SMEM_SZ>>>(x2p, w2p, b2, out);
    stats_final_kernel<<<HDIM, 256>>>(gamma2, beta2);

    bnrelu_kernel<<<(ROWS * HDIM / 4) / 256, 256>>>(out);
}

// round 13
// speedup vs baseline: 1.0916x; 1.0033x over previous
#include <cuda_runtime.h>
#include <cuda_fp16.h>
#include <cstdint>
#include <math.h>

// Problem constants (FP_Layer: B=8, N=8192, M=2048, C1=128, C2=256, H=256)
#define BB    8
#define NPTS  8192
#define MPTS  2048
#define C1    128
#define C2    256
#define HDIM  256
#define CIN   384
#define ROWS  (BB * NPTS)      // 65536
#define NPART 1024             // 512 m-tiles * 2 row-groups
#define KC    64               // K-chunk per stage

// ---------------- scratch (device globals; no allocation allowed) ----------
__device__ __align__(16) __half g_y1h[(size_t)ROWS * HDIM]; // 32 MB fp16 (raw y1)
__device__ __align__(16) __half g_x1[(size_t)ROWS * CIN];   // 48 MB fp16
__device__ __align__(16) __half g_x2[(size_t)ROWS * HDIM];  // 32 MB fp16
__device__ int   g_idx[ROWS * 3];
__device__ float g_w[ROWS * 3];
__device__ float g_psum[HDIM * NPART];          // [col][part] transposed
__device__ float g_psq[HDIM * NPART];
__device__ float g_a[HDIM];
__device__ float g_c[HDIM];
__device__ __align__(16) __half g_w1h[256 * 384];
__device__ __align__(16) __half g_w2h[256 * 256];

// ================= PTX helpers (baseline ISA, OK on compute_103) ============
__device__ __forceinline__ uint32_t smem_u32(const void* p) {
    uint32_t a;
    asm("{ .reg .u64 t; cvta.to.shared.u64 t, %1; cvt.u32.u64 %0, t; }" : "=r"(a) : "l"(p));
    return a;
}
__device__ __forceinline__ void cpa16(uint32_t s, const void* g) {
    asm volatile("cp.async.cg.shared.global [%0], [%1], 16;" :: "r"(s), "l"(g));
}
#define CP_COMMIT() asm volatile("cp.async.commit_group;" ::: "memory")
#define CP_WAIT2()  asm volatile("cp.async.wait_group 2;" ::: "memory")
#define CP_WAIT1()  asm volatile("cp.async.wait_group 1;" ::: "memory")
#define CP_WAIT0()  asm volatile("cp.async.wait_group 0;" ::: "memory")

__device__ __forceinline__ void ldsm4(uint32_t* r, uint32_t addr) {
    asm volatile("ldmatrix.sync.aligned.m8n8.x4.shared.b16 {%0,%1,%2,%3}, [%4];"
                 : "=r"(r[0]), "=r"(r[1]), "=r"(r[2]), "=r"(r[3]) : "r"(addr));
}
__device__ __forceinline__ void mma_f16(float* c, const uint32_t* a, const uint32_t* b) {
    asm volatile(
        "mma.sync.aligned.m16n8k16.row.col.f32.f16.f16.f32 "
        "{%0,%1,%2,%3}, {%4,%5,%6,%7}, {%8,%9}, {%0,%1,%2,%3};"
        : "+f"(c[0]), "+f"(c[1]), "+f"(c[2]), "+f"(c[3])
        : "r"(a[0]), "r"(a[1]), "r"(a[2]), "r"(a[3]), "r"(b[0]), "r"(b[1]));
}

// ---------------- 0) convert W to fp16 --------------------------------------
__global__ void __launch_bounds__(256) prep_w_kernel(const float* __restrict__ W1,
                                                     const float* __restrict__ W2) {
    int i = blockIdx.x * 256 + threadIdx.x;   // grid covers 256*384
    g_w1h[i] = __float2half_rn(W1[i]);
    if (i < 256 * 256) g_w2h[i] = __float2half_rn(W2[i]);
}

// ---------------- 1) 3-NN over xyz2 (4 independent compare chains) ---------
__global__ void __launch_bounds__(256) knn_kernel(const float* __restrict__ xyz1,
                                                  const float* __restrict__ xyz2) {
    __shared__ float4 s2[MPTS];               // x,y,z,|.|^2  (32KB)
    int b    = blockIdx.x >> 5;
    int tile = blockIdx.x & 31;
    const float* x2 = xyz2 + (size_t)b * MPTS * 3;
    for (int i = threadIdx.x; i < MPTS; i += 256) {
        float x = x2[i * 3 + 0], y = x2[i * 3 + 1], z = x2[i * 3 + 2];
        s2[i] = make_float4(x, y, z, x * x + y * y + z * z);
    }
    __syncthreads();

    int n = tile * 256 + threadIdx.x;
    int r = b * NPTS + n;
    float px = xyz1[(size_t)r * 3 + 0];
    float py = xyz1[(size_t)r * 3 + 1];
    float pz = xyz1[(size_t)r * 3 + 2];
    float pn = px * px + py * py + pz * pz;

    float cd[4][3];
    int   ci[4][3];
    #pragma unroll
    for (int j = 0; j < 4; j++) {
        cd[j][0] = cd[j][1] = cd[j][2] = 3.4e38f;
        ci[j][0] = ci[j][1] = ci[j][2] = 0;
    }
    for (int m = 0; m < MPTS; m += 4) {
        #pragma unroll
        for (int j = 0; j < 4; j++) {
            float4 t = s2[m + j];
            // identical formula to reference: |a|^2 + |b|^2 - 2 a.b
            float d = (pn + t.w) - 2.f * (px * t.x + py * t.y + pz * t.z);
            if (d < cd[j][2]) {
                if (d < cd[j][1]) {
                    cd[j][2] = cd[j][1]; ci[j][2] = ci[j][1];
                    if (d < cd[j][0]) {
                        cd[j][1] = cd[j][0]; ci[j][1] = ci[j][0];
                        cd[j][0] = d; ci[j][0] = m + j;
                    } else { cd[j][1] = d; ci[j][1] = m + j; }
                } else { cd[j][2] = d; ci[j][2] = m + j; }
            }
        }
    }
    // exact lexicographic (d, idx) merge of 12 candidates -> 3 smallest
    float md[12]; int mi[12];
    #pragma unroll
    for (int j = 0; j < 4; j++)
        #pragma unroll
        for (int k = 0; k < 3; k++) { md[j * 3 + k] = cd[j][k]; mi[j * 3 + k] = ci[j][k]; }
    float outd[3]; int outi[3];
    #pragma unroll
    for (int s = 0; s < 3; s++) {
        float bd = 3.5e38f; int bi = 0x7fffffff; int bk = 0;
        #pragma unroll
        for (int k = 0; k < 12; k++) {
            bool take = (md[k] < bd) || (md[k] == bd && mi[k] < bi);
            if (take) { bd = md[k]; bi = mi[k]; bk = k; }
        }
        outd[s] = bd; outi[s] = bi;
        md[bk] = 3.5e38f; mi[bk] = 0x7fffffff;
    }
    float r0 = 1.f / (outd[0] + 1e-8f);
    float r1 = 1.f / (outd[1] + 1e-8f);
    float r2 = 1.f / (outd[2] + 1e-8f);
    float s  = (r0 + r1) + r2;
    g_idx[r * 3 + 0] = outi[0]; g_idx[r * 3 + 1] = outi[1]; g_idx[r * 3 + 2] = outi[2];
    g_w[r * 3 + 0] = r0 / s; g_w[r * 3 + 1] = r1 / s; g_w[r * 3 + 2] = r2 / s;
}

// ---------------- 2) build x1 = fp16([points1 | interp(points2)]) -----------
__global__ void __launch_bounds__(256) prep_x1_kernel(const float* __restrict__ points1,
                                                      const float* __restrict__ P2) {
    const int idx = blockIdx.x * 256 + threadIdx.x;
    const int row = idx / 48;
    const int g8  = (idx % 48) * 8;
    __half2 out[4];
    if (g8 < C1) {
        const float* src = points1 + (size_t)row * C1 + g8;
        float4 f0 = *(const float4*)(src);
        float4 f1 = *(const float4*)(src + 4);
        out[0] = __floats2half2_rn(f0.x, f0.y);
        out[1] = __floats2half2_rn(f0.z, f0.w);
        out[2] = __floats2half2_rn(f1.x, f1.y);
        out[3] = __floats2half2_rn(f1.z, f1.w);
    } else {
        const int cc = g8 - C1;
        const float* p2b = P2 + (size_t)(row >> 13) * MPTS * C2;   // row / NPTS
        const float w0 = g_w[row * 3 + 0], w1 = g_w[row * 3 + 1], w2 = g_w[row * 3 + 2];
        const float* q0 = p2b + (size_t)g_idx[row * 3 + 0] * C2 + cc;
        const float* q1 = p2b + (size_t)g_idx[row * 3 + 1] * C2 + cc;
        const float* q2 = p2b + (size_t)g_idx[row * 3 + 2] * C2 + cc;
        #pragma unroll
        for (int h = 0; h < 2; h++) {
            float4 a = *(const float4*)(q0 + 4 * h);
            float4 b = *(const float4*)(q1 + 4 * h);
            float4 d = *(const float4*)(q2 + 4 * h);
            float v0 = a.x * w0 + b.x * w1 + d.x * w2;
            float v1 = a.y * w0 + b.y * w1 + d.y * w2;
            float v2 = a.z * w0 + b.z * w1 + d.z * w2;
            float v3 = a.w * w0 + b.w * w1 + d.w * w2;
            out[2 * h + 0] = __floats2half2_rn(v0, v1);
            out[2 * h + 1] = __floats2half2_rn(v2, v3);
        }
    }
    *(uint4*)(g_x1 + (size_t)row * CIN + g8) = *(uint4*)out;
}

// ---------------- 3) build x2 = fp16(relu(bn(y1h))) -------------------------
__global__ void __launch_bounds__(256) prep_x2_kernel() {
    __shared__ float sA[HDIM], sC[HDIM];
    sA[threadIdx.x] = g_a[threadIdx.x];
    sC[threadIdx.x] = g_c[threadIdx.x];
    __syncthreads();
    const int idx = blockIdx.x * 256 + threadIdx.x;
    const int row = idx / 32;
    const int c8  = (idx % 32) * 8;
    uint4 raw = *(const uint4*)(g_y1h + (size_t)row * HDIM + c8);
    const __half2* h = (const __half2*)&raw;
    __half2 out[4];
    #pragma unroll
    for (int j = 0; j < 4; j++) {
        float2 f = __half22float2(h[j]);
        const int g = c8 + 2 * j;
        out[j] = __floats2half2_rn(fmaxf(f.x * sA[g]     + sC[g],     0.f),
                                   fmaxf(f.y * sA[g + 1] + sC[g + 1], 0.f));
    }
    *(uint4*)(g_x2 + (size_t)row * HDIM + c8) = *(uint4*)out;
}

// ---------------- 4) streaming FP16 HMMA GEMM  C = A * W^T + bias -----------
// CTA tile 128(M) x 128(N), *** 128 threads / 4 warps, warp tile 64x64 ***
// (cuts ldsm traffic 96KB -> 64KB per chunk), KC=64, 3-stage cp.async ring,
// 2 CTAs/SM. grid = (ROWS/128, HDIM/128). HALF_OUT: store y as fp16.
#define PITCHB    144                      // bytes per row (72 halves)
#define OFF_BIAS  0
#define OFF_T     1024
#define A_SZ      (128 * PITCHB)           // 18432
#define B_SZ      (128 * PITCHB)           // 18432
#define STG_SZ    (A_SZ + B_SZ)            // 36864
#define OFF_A(s)  (OFF_T + (s) * STG_SZ)
#define OFF_B(s)  (OFF_A(s) + A_SZ)
#define SMEM_SZ   (OFF_T + 3 * STG_SZ)     // 111616 -> 2 CTAs/SM

template <int K, bool HALF_OUT>
__global__ void __launch_bounds__(128, 2) gemm_f16(const __half* __restrict__ Ah,
                                                   const __half* __restrict__ WH,
                                                   const float* __restrict__ bias,
                                                   void* __restrict__ dst_) {
    constexpr int NC = K / KC;
    extern __shared__ char smem[];
    const uint32_t sb = smem_u32(smem);
    const int tid = threadIdx.x, wid = tid >> 5, lane = tid & 31;
    const int rowBase = blockIdx.x * 128;
    const int nBase   = blockIdx.y * 128;

    float* sBias = (float*)(smem + OFF_BIAS);
    sBias[tid] = bias[nBase + tid];
    __syncthreads();

    auto fillB = [&](int c, int s) {
        const int kt = c * KC;
        const uint32_t base = sb + OFF_B(s);
        #pragma unroll
        for (int it = 0; it < 8; it++) {
            const int idx = tid + 128 * it;       // 0..1023
            const int n = idx >> 3, j = idx & 7;  // local W row, 16B chunk
            cpa16(base + (uint32_t)(n * PITCHB + j * 16),
                  WH + (size_t)(nBase + n) * K + kt + j * 8);
        }
    };
    auto fillA = [&](int c, int s) {
        const int kt = c * KC;
        const uint32_t base = sb + OFF_A(s);
        #pragma unroll
        for (int it = 0; it < 8; it++) {
            const int idx = tid + 128 * it;       // 0..1023
            const int n = idx >> 3, j = idx & 7;  // tile row, 16B chunk
            cpa16(base + (uint32_t)(n * PITCHB + j * 16),
                  Ah + (size_t)(rowBase + n) * K + kt + j * 8);
        }
    };

    // ---- warp layout: 2 row-groups (64 rows) x 2 col-groups (64 cols)
    const int rh = wid >> 1;          // row group
    const int cg = wid & 1;           // col group
    const int nb = cg * 64;

    // ---- accumulators init = bias (folded epilogue add)
    float acc[4][8][4];
    #pragma unroll
    for (int nt = 0; nt < 8; nt++) {
        const float b0 = sBias[nb + nt * 8 + 2 * (lane & 3)];
        const float b1 = sBias[nb + nt * 8 + 2 * (lane & 3) + 1];
        #pragma unroll
        for (int mt = 0; mt < 4; mt++) {
            acc[mt][nt][0] = b0; acc[mt][nt][1] = b1;
            acc[mt][nt][2] = b0; acc[mt][nt][3] = b1;
        }
    }

    // ldmatrix per-lane address parts (proven mapping)
    const uint32_t aRow = (uint32_t)(((lane >> 3) & 1) * 8 + (lane & 7));
    const uint32_t aK   = (uint32_t)((lane >> 4) * 8);
    const uint32_t bRow = (uint32_t)((lane >> 4) * 8 + (lane & 7));
    const uint32_t bK   = (uint32_t)(((lane >> 3) & 1) * 8);

    // ---- prologue: stages 0,1 in flight (2-chunk lookahead)
    fillA(0, 0); fillB(0, 0); CP_COMMIT();
    fillA(1, 1); fillB(1, 1); CP_COMMIT();

    #pragma unroll 1
    for (int c = 0; c < NC; c++) {
        const int s = c % 3;
        if (c > 0) __syncthreads();             // readers done with stage (c+2)%3
        if (c + 2 < NC) {
            const int s2 = (c + 2) % 3;
            fillA(c + 2, s2); fillB(c + 2, s2); CP_COMMIT();
            CP_WAIT2();
        } else if (c + 1 < NC) {
            CP_WAIT1();
        } else {
            CP_WAIT0();
        }
        __syncthreads();                        // stage c visible to all

        const uint32_t baseA = sb + OFF_A(0) + (uint32_t)s * STG_SZ;
        const uint32_t baseB = baseA + A_SZ;

        #pragma unroll
        for (int kk = 0; kk < 4; kk++) {
            uint32_t a[4][4], bh[4][4];
            #pragma unroll
            for (int mt = 0; mt < 4; mt++)
                ldsm4(a[mt], baseA + (rh * 64 + mt * 16 + aRow) * PITCHB + (kk * 16 + aK) * 2);
            #pragma unroll
            for (int p = 0; p < 4; p++)
                ldsm4(bh[p], baseB + (nb + p * 16 + bRow) * PITCHB + (kk * 16 + bK) * 2);
            #pragma unroll
            for (int mt = 0; mt < 4; mt++)
                #pragma unroll
                for (int nt = 0; nt < 8; nt++)
                    // f16 B frag = consecutive regs: nt even {r0,r1}, odd {r2,r3}
                    mma_f16(acc[mt][nt], a[mt], &bh[nt >> 1][(nt & 1) * 2]);
        }
    }

    // ---- epilogue 1: per-(m-tile,row-group) BN partials (transposed)
    {
        const int part = blockIdx.x * 2 + rh;
        #pragma unroll
        for (int nt = 0; nt < 8; nt++) {
            float s0 = 0.f, s1 = 0.f, q0 = 0.f, q1 = 0.f;
            #pragma unroll
            for (int mt = 0; mt < 4; mt++) {
                float v0 = acc[mt][nt][0], v1 = acc[mt][nt][1];
                float v2 = acc[mt][nt][2], v3 = acc[mt][nt][3];
                s0 += v0 + v2;  s1 += v1 + v3;
                q0 += v0 * v0 + v2 * v2;  q1 += v1 * v1 + v3 * v3;
            }
            #pragma unroll
            for (int o = 4; o < 32; o <<= 1) {
                s0 += __shfl_xor_sync(0xffffffffu, s0, o);
                s1 += __shfl_xor_sync(0xffffffffu, s1, o);
                q0 += __shfl_xor_sync(0xffffffffu, q0, o);
                q1 += __shfl_xor_sync(0xffffffffu, q1, o);
            }
            if (lane < 4) {
                const int col = nBase + nb + nt * 8 + 2 * lane;
                g_psum[(size_t)col * NPART + part]       = s0;
                g_psum[(size_t)(col + 1) * NPART + part] = s1;
                g_psq[(size_t)col * NPART + part]        = q0;
                g_psq[(size_t)(col + 1) * NPART + part]  = q1;
            }
        }
    }

    // ---- epilogue 2: store y (fp16 for layer-1, fp32 for final layer)
    #pragma unroll
    for (int mt = 0; mt < 4; mt++) {
        const int row = rowBase + rh * 64 + mt * 16 + (lane >> 2);
        #pragma unroll
        for (int nt = 0; nt < 8; nt++) {
            const int col = nBase + nb + nt * 8 + 2 * (lane & 3);
            if (HALF_OUT) {
                __half* dh = (__half*)dst_;
                *(__half2*)(dh + (size_t)row * HDIM + col) =
                    __floats2half2_rn(acc[mt][nt][0], acc[mt][nt][1]);
                *(__half2*)(dh + (size_t)(row + 8) * HDIM + col) =
                    __floats2half2_rn(acc[mt][nt][2], acc[mt][nt][3]);
            } else {
                float* df = (float*)dst_;
                float2 v0 = {acc[mt][nt][0], acc[mt][nt][1]};
                float2 v1 = {acc[mt][nt][2], acc[mt][nt][3]};
                *(float2*)(df + (size_t)row * HDIM + col)       = v0;
                *(float2*)(df + (size_t)(row + 8) * HDIM + col) = v1;
            }
        }
    }
}

// ---------------- 5) BN stats final reduce (one block per channel) ----------
__global__ void __launch_bounds__(256) stats_final_kernel(const float* __restrict__ gamma,
                                                          const float* __restrict__ beta) {
    const int ch = blockIdx.x;
    const int t  = threadIdx.x;
    const float* ps = g_psum + (size_t)ch * NPART;
    const float* pq = g_psq + (size_t)ch * NPART;
    float s = 0.f, q = 0.f;
    #pragma unroll
    for (int k = 0; k < NPART / 256; k++) {
        s += ps[t + 256 * k];
        q += pq[t + 256 * k];
    }
    __shared__ float ss[256], sq[256];
    ss[t] = s; sq[t] = q;
    __syncthreads();
    #pragma unroll
    for (int o = 128; o >= 32; o >>= 1) {
        if (t < o) { ss[t] += ss[t + o]; sq[t] += sq[t + o]; }
        __syncthreads();
    }
    if (t < 32) {
        s = ss[t]; q = sq[t];
        #pragma unroll
        for (int o = 16; o > 0; o >>= 1) {
            s += __shfl_xor_sync(0xffffffffu, s, o);
            q += __shfl_xor_sync(0xffffffffu, q, o);
        }
        if (t == 0) {
            const float mean = s * (1.f / (float)ROWS);
            const float var  = q * (1.f / (float)ROWS) - mean * mean;
            const float a    = gamma[ch] * rsqrtf(var + 1e-5f);
            g_a[ch] = a;
            g_c[ch] = beta[ch] - mean * a;
        }
    }
}

// ---------------- 6) in-place bn+relu on d_out ------------------------------
__global__ void __launch_bounds__(256) bnrelu_kernel(float* __restrict__ out) {
    size_t i = (size_t)blockIdx.x * 256 + threadIdx.x;   // float4 index
    float4* o4 = (float4*)out;
    float4 v = o4[i];
    int c = (int)((i << 2) & (HDIM - 1));
    v.x = fmaxf(v.x * g_a[c + 0] + g_c[c + 0], 0.f);
    v.y = fmaxf(v.y * g_a[c + 1] + g_c[c + 1], 0.f);
    v.z = fmaxf(v.z * g_a[c + 2] + g_c[c + 2], 0.f);
    v.w = fmaxf(v.w * g_a[c + 3] + g_c[c + 3], 0.f);
    o4[i] = v;
}

// ---------------- host ------------------------------------------------------
extern "C" void kernel_launch(void* const* d_in, const int* in_sizes, int n_in,
                              void* d_out, int out_size) {
    const float* xyz1    = (const float*)d_in[0];
    const float* xyz2    = (const float*)d_in[1];
    const float* points1 = (const float*)d_in[2];
    const float* points2 = (const float*)d_in[3];
    const float* W1      = (const float*)d_in[4];
    const float* b1      = (const float*)d_in[5];
    const float* gamma1  = (const float*)d_in[6];
    const float* beta1   = (const float*)d_in[7];
    const float* W2      = (const float*)d_in[8];
    const float* b2      = (const float*)d_in[9];
    const float* gamma2  = (const float*)d_in[10];
    const float* beta2   = (const float*)d_in[11];
    float* out = (float*)d_out;

    cudaFuncSetAttribute(gemm_f16<CIN, true>,   cudaFuncAttributeMaxDynamicSharedMemorySize, SMEM_SZ);
    cudaFuncSetAttribute(gemm_f16<HDIM, false>, cudaFuncAttributeMaxDynamicSharedMemorySize, SMEM_SZ);

    __half *x1p = nullptr, *x2p = nullptr, *w1p = nullptr, *w2p = nullptr, *y1p = nullptr;
    cudaGetSymbolAddress((void**)&x1p, g_x1);
    cudaGetSymbolAddress((void**)&x2p, g_x2);
    cudaGetSymbolAddress((void**)&w1p, g_w1h);
    cudaGetSymbolAddress((void**)&w2p, g_w2h);
    cudaGetSymbolAddress((void**)&y1p, g_y1h);

    prep_w_kernel<<<(256 * 384) / 256, 256>>>(W1, W2);
    knn_kernel<<<BB * (NPTS / 256), 256>>>(xyz1, xyz2);
    prep_x1_kernel<<<(ROWS * 48) / 256, 256>>>(points1, points2);

    gemm_f16<CIN, true><<<dim3(ROWS / 128, HDIM / 128), 128, SMEM_SZ>>>(x1p, w1p, b1, y1p);
    stats_final_kernel<<<HDIM, 256>>>(gamma1, beta1);
    prep_x2_kernel<<<(ROWS * 32) / 256, 256>>>();

    gemm_f16<HDIM, false><<<dim3(ROWS / 128, HDIM / 128), 128, SMEM_SZ>>>(x2p, w2p, b2, out);
    stats_final_kernel<<<HDIM, 256>>>(gamma2, beta2);

    bnrelu_kernel<<<(ROWS * HDIM / 4) / 256, 256>>>(out);
}